// round 1
// baseline (speedup 1.0000x reference)
#include <cuda_runtime.h>

// Problem constants (from reference: B=4, T=12, N=4096, F=32, NG=14)
#define Bq 4
#define Tq 12
#define Nq 4096
#define Fq 32

// ---------------------------------------------------------------------------
// Device scratch (allocation-free rule: __device__ globals)
// ---------------------------------------------------------------------------
__device__ float g_YX[(size_t)Bq * Tq * Nq * Fq];   // adj @ x, all timesteps
__device__ float g_Y1[(size_t)Bq * Nq * 2 * Fq];    // adj @ [h | m]
__device__ float g_Y2[(size_t)Bq * Nq * Fq];        // adj @ h_mid
__device__ float g_S [(size_t)Bq * Nq * 2 * Fq];    // state: [h | m] packed per row
__device__ float g_c [(size_t)Bq * Nq * Fq];        // cell state
__device__ float g_hmid[(size_t)Bq * Nq * Fq];      // h_mid

__device__ __forceinline__ float sigf(float x) { return 1.0f / (1.0f + __expf(-x)); }

// ---------------------------------------------------------------------------
// init: h = c = m = 1
// ---------------------------------------------------------------------------
__global__ void init_state() {
    int i = blockIdx.x * blockDim.x + threadIdx.x;
    if (i < Bq * Nq * 2 * Fq) g_S[i] = 1.0f;
    if (i < Bq * Nq * Fq)     g_c[i] = 1.0f;
}

// ---------------------------------------------------------------------------
// adj GEMM: Y[z] = adj[z/div] @ V[z], A is [N,N] row-major, V/Y are [N,BN].
// BM=128, BK=16, 256 threads, thread tile 8 x (BN/16). Register prefetch.
// ---------------------------------------------------------------------------
template <int BN>
__global__ __launch_bounds__(256) void adj_gemm(const float* __restrict__ adj,
                                                const float* __restrict__ V,
                                                float* __restrict__ Y, int div) {
    constexpr int BM = 128, BK = 16;
    constexpr int TN = BN / 16;   // 4 for BN=64, 2 for BN=32
    __shared__ float As[BK][BM + 4];  // transposed, padded
    __shared__ float Bs[BK][BN];

    const int tid = threadIdx.x;
    const int tx = tid & 15, ty = tid >> 4;
    const int z = blockIdx.z;

    const float* A  = adj + (size_t)(z / div) * Nq * Nq + (size_t)(blockIdx.x * BM) * Nq;
    const float* Vz = V   + (size_t)z * Nq * BN;
    float*       Yz = Y   + (size_t)z * Nq * BN + (size_t)(blockIdx.x * BM) * BN;

    // A loader: 2 x float4 per thread (rows ar and ar+64, cols ac..ac+3)
    const int ar = tid >> 2;
    const int ac = (tid & 3) << 2;
    // B loader
    const int  bkr  = (BN == 64) ? (tid >> 4) : (tid >> 3);
    const int  bnc  = (BN == 64) ? ((tid & 15) << 2) : ((tid & 7) << 2);
    const bool bact = (BN == 64) || (tid < 128);

    float acc[8][TN];
#pragma unroll
    for (int r = 0; r < 8; r++)
#pragma unroll
        for (int c = 0; c < TN; c++) acc[r][c] = 0.0f;

    float4 pa0 = *(const float4*)(A + (size_t)ar * Nq + ac);
    float4 pa1 = *(const float4*)(A + (size_t)(ar + 64) * Nq + ac);
    float4 pb  = make_float4(0.f, 0.f, 0.f, 0.f);
    if (bact) pb = *(const float4*)(Vz + (size_t)bkr * BN + bnc);

    for (int k0 = 0; k0 < Nq; k0 += BK) {
        // commit prefetched tile to smem
        As[ac + 0][ar] = pa0.x; As[ac + 1][ar] = pa0.y;
        As[ac + 2][ar] = pa0.z; As[ac + 3][ar] = pa0.w;
        As[ac + 0][ar + 64] = pa1.x; As[ac + 1][ar + 64] = pa1.y;
        As[ac + 2][ar + 64] = pa1.z; As[ac + 3][ar + 64] = pa1.w;
        if (bact) *(float4*)&Bs[bkr][bnc] = pb;
        __syncthreads();

        if (k0 + BK < Nq) {
            pa0 = *(const float4*)(A + (size_t)ar * Nq + (k0 + BK) + ac);
            pa1 = *(const float4*)(A + (size_t)(ar + 64) * Nq + (k0 + BK) + ac);
            if (bact) pb = *(const float4*)(Vz + (size_t)(k0 + BK + bkr) * BN + bnc);
        }

#pragma unroll
        for (int k = 0; k < BK; k++) {
            float4 av0 = *(const float4*)&As[k][ty * 8];
            float4 av1 = *(const float4*)&As[k][ty * 8 + 4];
            float a[8] = {av0.x, av0.y, av0.z, av0.w, av1.x, av1.y, av1.z, av1.w};
            float bv[TN];
            if constexpr (TN == 4) {
                float4 b4 = *(const float4*)&Bs[k][tx * 4];
                bv[0] = b4.x; bv[1] = b4.y; bv[2] = b4.z; bv[3] = b4.w;
            } else {
                float2 b2 = *(const float2*)&Bs[k][tx * 2];
                bv[0] = b2.x; bv[1] = b2.y;
            }
#pragma unroll
            for (int r = 0; r < 8; r++)
#pragma unroll
                for (int c = 0; c < TN; c++)
                    acc[r][c] = fmaf(a[r], bv[c], acc[r][c]);
        }
        __syncthreads();
    }

#pragma unroll
    for (int r = 0; r < 8; r++) {
        float* yp = Yz + (size_t)(ty * 8 + r) * BN + tx * TN;
        if constexpr (TN == 4) {
            *(float4*)yp = make_float4(acc[r][0], acc[r][1], acc[r][2], acc[r][3]);
        } else {
            *(float2*)yp = make_float2(acc[r][0], acc[r][1]);
        }
    }
}

// ---------------------------------------------------------------------------
// gates1: LSTM gates (0..7). Per row n (warp): yx = YX[b,t,n,:], yh = Y1[...,0:32].
// g(i,v) = GLU(y @ W[i] + b[i]).  f=sig(g0+g1), i=sig(g2+g3), o=sig(g6+g7),
// c_new = f*c + i*tanh(g4+g5), h_mid = o*tanh(c_new).
// W packed in dyn smem as float4 {Wx[k][l], Wx[k][l+32], Wh[k][l], Wh[k][l+32]}
// per (k, pair p, lane l), layout [k*128 + p*32 + l] -> conflict-free LDS.128.
// ---------------------------------------------------------------------------
__global__ __launch_bounds__(256) void gates1_kernel(const float* __restrict__ W,
                                                     const float* __restrict__ bias,
                                                     int t, float* __restrict__ last_c) {
    extern __shared__ float sm[];
    float4* Wp = (float4*)sm;                 // 4096 float4 = 65536 B
    float4* bp = (float4*)(sm + 16384);       // 128  float4 =  2048 B
    float2* ys = (float2*)(sm + 16384 + 512); // 256  float2 =  2048 B

    const int tid = threadIdx.x;
    for (int idx = tid; idx < 4096; idx += 256) {
        int l = idx & 31, p = (idx >> 5) & 3, k = idx >> 7;
        const float* W0 = W + (2 * p) * (Fq * 2 * Fq) + k * (2 * Fq);
        const float* W1 = W + (2 * p + 1) * (Fq * 2 * Fq) + k * (2 * Fq);
        Wp[idx] = make_float4(W0[l], W0[l + 32], W1[l], W1[l + 32]);
    }
    if (tid < 128) {
        int l = tid & 31, p = tid >> 5;
        bp[p * 32 + l] = make_float4(bias[(2 * p) * 64 + l], bias[(2 * p) * 64 + 32 + l],
                                     bias[(2 * p + 1) * 64 + l], bias[(2 * p + 1) * 64 + 32 + l]);
    }
    __syncthreads();

    const int w = tid >> 5, l = tid & 31;
    const int nrows = Bq * Nq;
    for (int row = blockIdx.x * 8 + w; row < nrows; row += gridDim.x * 8) {
        int b = row >> 12, n = row & (Nq - 1);
        float yx = g_YX[(((size_t)b * Tq + t) * Nq + n) * Fq + l];
        float yh = g_Y1[(size_t)row * (2 * Fq) + l];
        ys[w * 32 + l] = make_float2(yx, yh);
        __syncwarp();

        float acc[4][4];
#pragma unroll
        for (int p = 0; p < 4; p++)
#pragma unroll
            for (int q = 0; q < 4; q++) acc[p][q] = 0.0f;

#pragma unroll
        for (int k = 0; k < 32; k++) {
            float2 y = ys[w * 32 + k];
#pragma unroll
            for (int p = 0; p < 4; p++) {
                float4 wv = Wp[k * 128 + p * 32 + l];
                acc[p][0] = fmaf(y.x, wv.x, acc[p][0]);
                acc[p][1] = fmaf(y.x, wv.y, acc[p][1]);
                acc[p][2] = fmaf(y.y, wv.z, acc[p][2]);
                acc[p][3] = fmaf(y.y, wv.w, acc[p][3]);
            }
        }
        __syncwarp();

        float s[4];
#pragma unroll
        for (int p = 0; p < 4; p++) {
            float4 bb = bp[p * 32 + l];
            float gx = (acc[p][0] + bb.x) * sigf(acc[p][1] + bb.y);
            float gh = (acc[p][2] + bb.z) * sigf(acc[p][3] + bb.w);
            s[p] = gx + gh;
        }
        float f  = sigf(s[0]);
        float ig = sigf(s[1]);
        float o  = sigf(s[3]);
        size_t ci = (size_t)row * Fq + l;
        float cn = f * g_c[ci] + ig * tanhf(s[2]);
        g_c[ci] = cn;
        g_hmid[ci] = o * tanhf(cn);
        if (t == Tq - 1) last_c[ci] = cn;
    }
}

// ---------------------------------------------------------------------------
// gates2: memory gates (8..13). y2 = Y2 (adj@h_mid), ym = Y1[...,32:64] (adj@m).
// i2=sig(g8+g9), gg=sig(g10+g11), o2=sig(g12+g13);
// m_new = i2*m + (1-i2)*gg; h_new = m_new*o2.
// ---------------------------------------------------------------------------
__global__ __launch_bounds__(256) void gates2_kernel(const float* __restrict__ W8,
                                                     const float* __restrict__ bias8,
                                                     int t, float* __restrict__ hidden,
                                                     float* __restrict__ last_h,
                                                     float* __restrict__ last_m) {
    extern __shared__ float sm[];
    float4* Wp = (float4*)sm;                 // 3072 float4 = 49152 B
    float4* bp = (float4*)(sm + 12288);       //   96 float4 =  1536 B
    float2* ys = (float2*)(sm + 12288 + 384); //  256 float2 =  2048 B

    const int tid = threadIdx.x;
    for (int idx = tid; idx < 3072; idx += 256) {
        int k = idx / 96, r = idx % 96, p = r >> 5, l = r & 31;
        const float* W0 = W8 + (2 * p) * (Fq * 2 * Fq) + k * (2 * Fq);
        const float* W1 = W8 + (2 * p + 1) * (Fq * 2 * Fq) + k * (2 * Fq);
        Wp[idx] = make_float4(W0[l], W0[l + 32], W1[l], W1[l + 32]);
    }
    if (tid < 96) {
        int p = tid >> 5, l = tid & 31;
        bp[tid] = make_float4(bias8[(2 * p) * 64 + l], bias8[(2 * p) * 64 + 32 + l],
                              bias8[(2 * p + 1) * 64 + l], bias8[(2 * p + 1) * 64 + 32 + l]);
    }
    __syncthreads();

    const int w = tid >> 5, l = tid & 31;
    const int nrows = Bq * Nq;
    for (int row = blockIdx.x * 8 + w; row < nrows; row += gridDim.x * 8) {
        int b = row >> 12, n = row & (Nq - 1);
        float y2 = g_Y2[(size_t)row * Fq + l];
        float ym = g_Y1[(size_t)row * (2 * Fq) + 32 + l];
        ys[w * 32 + l] = make_float2(y2, ym);
        __syncwarp();

        float acc[3][4];
#pragma unroll
        for (int p = 0; p < 3; p++)
#pragma unroll
            for (int q = 0; q < 4; q++) acc[p][q] = 0.0f;

#pragma unroll
        for (int k = 0; k < 32; k++) {
            float2 y = ys[w * 32 + k];
#pragma unroll
            for (int p = 0; p < 3; p++) {
                float4 wv = Wp[k * 96 + p * 32 + l];
                acc[p][0] = fmaf(y.x, wv.x, acc[p][0]);
                acc[p][1] = fmaf(y.x, wv.y, acc[p][1]);
                acc[p][2] = fmaf(y.y, wv.z, acc[p][2]);
                acc[p][3] = fmaf(y.y, wv.w, acc[p][3]);
            }
        }
        __syncwarp();

        float s[3];
#pragma unroll
        for (int p = 0; p < 3; p++) {
            float4 bb = bp[p * 32 + l];
            float gx = (acc[p][0] + bb.x) * sigf(acc[p][1] + bb.y);
            float gh = (acc[p][2] + bb.z) * sigf(acc[p][3] + bb.w);
            s[p] = gx + gh;
        }
        float i2 = sigf(s[0]);
        float gg = sigf(s[1]);
        float o2 = sigf(s[2]);
        float mo = g_S[(size_t)row * (2 * Fq) + 32 + l];
        float mn = i2 * mo + (1.0f - i2) * gg;
        float hn = mn * o2;
        g_S[(size_t)row * (2 * Fq) + l]      = hn;
        g_S[(size_t)row * (2 * Fq) + 32 + l] = mn;
        hidden[(((size_t)b * Tq + t) * Nq + n) * Fq + l] = hn;
        if (t == Tq - 1) {
            last_h[(size_t)row * Fq + l] = hn;
            last_m[(size_t)row * Fq + l] = mn;
        }
    }
}

// ---------------------------------------------------------------------------
// kernel_launch: graph-capturable, allocation-free.
// Inputs: x [B,T,N,F] f32, adj [B,N,N] f32, W [14,F,2F] f32, b [14,2F] f32.
// Output: concat(hidden_states [B,T,N,F], last_h, last_c, last_m) f32.
// ---------------------------------------------------------------------------
extern "C" void kernel_launch(void* const* d_in, const int* in_sizes, int n_in,
                              void* d_out, int out_size) {
    (void)in_sizes; (void)n_in; (void)out_size;
    const float* x    = (const float*)d_in[0];
    const float* adj  = (const float*)d_in[1];
    const float* W    = (const float*)d_in[2];
    const float* bias = (const float*)d_in[3];

    float* hidden = (float*)d_out;
    float* last_h = hidden + (size_t)Bq * Tq * Nq * Fq;
    float* last_c = last_h + (size_t)Bq * Nq * Fq;
    float* last_m = last_c + (size_t)Bq * Nq * Fq;

    float *pYX, *pY1, *pY2, *pS, *pHmid;
    cudaGetSymbolAddress((void**)&pYX,   g_YX);
    cudaGetSymbolAddress((void**)&pY1,   g_Y1);
    cudaGetSymbolAddress((void**)&pY2,   g_Y2);
    cudaGetSymbolAddress((void**)&pS,    g_S);
    cudaGetSymbolAddress((void**)&pHmid, g_hmid);

    const int G1_SMEM = (16384 + 512 + 512) * 4;   // 69632 B
    const int G2_SMEM = (12288 + 384 + 512) * 4;   // 52736 B
    cudaFuncSetAttribute(gates1_kernel, cudaFuncAttributeMaxDynamicSharedMemorySize, G1_SMEM);
    cudaFuncSetAttribute(gates2_kernel, cudaFuncAttributeMaxDynamicSharedMemorySize, G2_SMEM);

    // h = c = m = 1
    init_state<<<(Bq * Nq * 2 * Fq + 255) / 256, 256>>>();

    // Precompute adj @ x for all (b, t): grid.z = 48, adj batch = z / T
    adj_gemm<32><<<dim3(Nq / 128, 1, Bq * Tq), 256>>>(adj, x, pYX, Tq);

    for (int t = 0; t < Tq; t++) {
        // Y1 = adj @ [h | m]  (width 64, one adj pass for both states)
        adj_gemm<64><<<dim3(Nq / 128, 1, Bq), 256>>>(adj, pS, pY1, 1);
        gates1_kernel<<<128, 256, G1_SMEM>>>(W, bias, t, last_c);
        // Y2 = adj @ h_mid
        adj_gemm<32><<<dim3(Nq / 128, 1, Bq), 256>>>(adj, pHmid, pY2, 1);
        gates2_kernel<<<128, 256, G2_SMEM>>>(W + 8 * (Fq * 2 * Fq), bias + 8 * (2 * Fq),
                                             t, hidden, last_h, last_m);
    }
}

// round 3
// speedup vs baseline: 1.9588x; 1.9588x over previous
#include <cuda_runtime.h>
#include <cuda_bf16.h>
#include <cstdint>

#define Bq 4
#define Tq 12
#define Nq 4096
#define Fq 32

// ---------------------------------------------------------------------------
// PTX helpers — Ampere-era only (valid at compute_103; no tcgen05/TMEM)
// ---------------------------------------------------------------------------
__device__ __forceinline__ uint32_t smem_to_u32(const void* p) {
    uint32_t a;
    asm("{ .reg .u64 t; cvta.to.shared.u64 t, %1; cvt.u32.u64 %0, t; }" : "=r"(a) : "l"(p));
    return a;
}

#define CP_ASYNC16(dst, src) \
    asm volatile("cp.async.cg.shared.global [%0], [%1], 16;" :: "r"(dst), "l"(src) : "memory")
#define CP_COMMIT() asm volatile("cp.async.commit_group;" ::: "memory")
#define CP_WAIT0()  asm volatile("cp.async.wait_group 0;" ::: "memory")
#define CP_WAIT1()  asm volatile("cp.async.wait_group 1;" ::: "memory")

__device__ __forceinline__ void ldsm4(uint32_t addr, uint32_t* r) {
    asm volatile("ldmatrix.sync.aligned.m8n8.x4.shared.b16 {%0,%1,%2,%3}, [%4];"
                 : "=r"(r[0]), "=r"(r[1]), "=r"(r[2]), "=r"(r[3]) : "r"(addr));
}
__device__ __forceinline__ void mma16816(float* d, const uint32_t* a, uint32_t b0, uint32_t b1) {
    asm volatile("mma.sync.aligned.m16n8k16.row.col.f32.bf16.bf16.f32 "
                 "{%0,%1,%2,%3},{%4,%5,%6,%7},{%8,%9},{%0,%1,%2,%3};"
                 : "+f"(d[0]), "+f"(d[1]), "+f"(d[2]), "+f"(d[3])
                 : "r"(a[0]), "r"(a[1]), "r"(a[2]), "r"(a[3]), "r"(b0), "r"(b1));
}

// ---------------------------------------------------------------------------
// Device scratch (16B-aligned for cp.async / vector access)
// ---------------------------------------------------------------------------
__device__ __align__(128) __nv_bfloat16 g_Ahi[(size_t)Bq * Nq * Nq];
__device__ __align__(128) __nv_bfloat16 g_Alo[(size_t)Bq * Nq * Nq];
__device__ __align__(128) __nv_bfloat16 g_xth[(size_t)Bq * Tq * Fq * Nq];  // [b][t*32+f][n]
__device__ __align__(128) __nv_bfloat16 g_xtl[(size_t)Bq * Tq * Fq * Nq];
__device__ __align__(128) __nv_bfloat16 g_Sth[(size_t)Bq * 2 * Fq * Nq];   // [b][64][n]  (h|m)
__device__ __align__(128) __nv_bfloat16 g_Stl[(size_t)Bq * 2 * Fq * Nq];
__device__ __align__(128) __nv_bfloat16 g_hth[(size_t)Bq * Fq * Nq];       // [b][32][n]  (h_mid)
__device__ __align__(128) __nv_bfloat16 g_htl[(size_t)Bq * Fq * Nq];

__device__ __align__(128) float g_YX[(size_t)Bq * Tq * Nq * Fq];
__device__ __align__(128) float g_Y1[(size_t)Bq * Nq * 2 * Fq];
__device__ __align__(128) float g_Y2[(size_t)Bq * Nq * Fq];
__device__ __align__(128) float g_S [(size_t)Bq * Nq * 2 * Fq];
__device__ __align__(128) float g_c [(size_t)Bq * Nq * Fq];
__device__ __align__(128) float g_hmid[(size_t)Bq * Nq * Fq];

__device__ __forceinline__ float sigf(float x) { return 1.0f / (1.0f + __expf(-x)); }

// ---------------------------------------------------------------------------
// adj -> bf16 hi/lo split
// ---------------------------------------------------------------------------
__global__ __launch_bounds__(256) void convert_adj(const float* __restrict__ adj) {
    size_t i = (size_t)blockIdx.x * 256 + threadIdx.x;
    float4 v = ((const float4*)adj)[i];
    __nv_bfloat16 h0 = __float2bfloat16(v.x), h1 = __float2bfloat16(v.y);
    __nv_bfloat16 h2 = __float2bfloat16(v.z), h3 = __float2bfloat16(v.w);
    __nv_bfloat16 l0 = __float2bfloat16(v.x - __bfloat162float(h0));
    __nv_bfloat16 l1 = __float2bfloat16(v.y - __bfloat162float(h1));
    __nv_bfloat16 l2 = __float2bfloat16(v.z - __bfloat162float(h2));
    __nv_bfloat16 l3 = __float2bfloat16(v.w - __bfloat162float(h3));
    __nv_bfloat162 hp0 = {h0, h1}, hp1 = {h2, h3}, lp0 = {l0, l1}, lp1 = {l2, l3};
    uint2 hw, lw;
    hw.x = *(uint32_t*)&hp0; hw.y = *(uint32_t*)&hp1;
    lw.x = *(uint32_t*)&lp0; lw.y = *(uint32_t*)&lp1;
    ((uint2*)g_Ahi)[i] = hw;
    ((uint2*)g_Alo)[i] = lw;
}

__global__ void init_state() {
    int i = blockIdx.x * blockDim.x + threadIdx.x;
    if (i < Bq * Nq * 2 * Fq) g_S[i] = 1.0f;
    if (i < Bq * Nq * Fq)     g_c[i] = 1.0f;
}

// ---------------------------------------------------------------------------
// transpose + bf16 split: V [z][4096][W] fp32 -> Thi/Tlo [z][W][4096] bf16
// ---------------------------------------------------------------------------
template <int W>
__global__ __launch_bounds__(256) void trans_split(const float* __restrict__ V, long long inZ,
                                                   __nv_bfloat16* __restrict__ Thi,
                                                   __nv_bfloat16* __restrict__ Tlo, long long outZ) {
    __shared__ float tile[64][W + 1];
    const int z = blockIdx.z;
    const int n0 = blockIdx.x * 64;
    const float* v = V + (size_t)z * inZ + (size_t)n0 * W;
    const int tid = threadIdx.x;
#pragma unroll
    for (int idx = tid; idx < 64 * W; idx += 256)
        tile[idx / W][idx % W] = v[idx];
    __syncthreads();
    __nv_bfloat16* th = Thi + (size_t)z * outZ;
    __nv_bfloat16* tl = Tlo + (size_t)z * outZ;
#pragma unroll
    for (int idx = tid; idx < 64 * W; idx += 256) {
        int f = idx >> 6, j = idx & 63;
        float val = tile[j][f];
        __nv_bfloat16 hi = __float2bfloat16(val);
        __nv_bfloat16 lo = __float2bfloat16(val - __bfloat162float(hi));
        th[(size_t)f * Nq + n0 + j] = hi;
        tl[(size_t)f * Nq + n0 + j] = lo;
    }
}

// ---------------------------------------------------------------------------
// split-bf16 mma.sync GEMM: Y[z] = adj[z/adiv] @ V[z]
// A [128 rows][K] bf16 hi/lo (row-major); B = V^T [BN rows][K] bf16 hi/lo.
// D = Ahi*Bhi^T + Ahi*Blo^T + Alo*Bhi^T, fp32 accumulators (in registers).
// BM=128, BK=32, 8 warps arranged 4(m) x 2(n). cp.async double-buffered.
// Output col j -> Y[z*yZ + row*rstride + (j>>5)*gstride + (j&31)].
// ---------------------------------------------------------------------------
template <int BN>
__global__ __launch_bounds__(256) void adj_gemm_mma(
    const __nv_bfloat16* __restrict__ Bhi_g, const __nv_bfloat16* __restrict__ Blo_g,
    long long bZ, int adiv, float* __restrict__ Y, long long yZ,
    int rstride, long long gstride) {
    constexpr int RB = 80;                 // smem row stride in bytes (64B data + 16B pad)
    constexpr int A_BYTES = 128 * RB;      // 10240
    constexpr int B_BYTES = BN * RB;
    constexpr int OFF_AH = 0, OFF_AL = A_BYTES;
    constexpr int OFF_BH = 2 * A_BYTES, OFF_BL = 2 * A_BYTES + B_BYTES;
    constexpr int STAGE = 2 * A_BYTES + 2 * B_BYTES;
    constexpr int WN = BN / 2;             // warp n-extent
    constexpr int NF = WN / 8;             // n-fragments per warp (4 or 2)
    constexpr int NB = (NF + 1) / 2;       // ldmatrix.x4 n-blocks (2 or 1)
    constexpr int NC = Nq / 32;            // 128 k-chunks

    extern __shared__ char smc[];
    const uint32_t sbase = smem_to_u32(smc);
    const int tid = threadIdx.x;
    const int wid = tid >> 5, lane = tid & 31;
    const int wm = wid & 3, wn = wid >> 2;
    const int z = blockIdx.z;
    const int m0 = blockIdx.x * 128;

    const __nv_bfloat16* gAh = g_Ahi + (size_t)(z / adiv) * Nq * Nq + (size_t)m0 * Nq;
    const __nv_bfloat16* gAl = g_Alo + (size_t)(z / adiv) * Nq * Nq + (size_t)m0 * Nq;
    const __nv_bfloat16* gBh = Bhi_g + (size_t)z * bZ;
    const __nv_bfloat16* gBl = Blo_g + (size_t)z * bZ;

    // loader indices
    const int arow = tid >> 2;             // 0..63 (+64 for rep 1)
    const int acol = tid & 3;              // 16B chunk
    const int brow = tid >> 2;
    const bool bact = (BN == 64) || (tid < 128);

    float acc[2][NF][4];
#pragma unroll
    for (int mf = 0; mf < 2; mf++)
#pragma unroll
        for (int nf = 0; nf < NF; nf++)
#pragma unroll
            for (int q = 0; q < 4; q++) acc[mf][nf][q] = 0.0f;

    auto issue = [&](int c) {
        const uint32_t st = sbase + (uint32_t)(c & 1) * STAGE;
        const int k0 = c * 32;
#pragma unroll
        for (int rep = 0; rep < 2; rep++) {
            int r = rep * 64 + arow;
            uint32_t d = st + r * RB + acol * 16;
            const __nv_bfloat16* sh = gAh + (size_t)r * Nq + k0 + acol * 8;
            const __nv_bfloat16* sl = gAl + (size_t)r * Nq + k0 + acol * 8;
            CP_ASYNC16(d + OFF_AH, sh);
            CP_ASYNC16(d + OFF_AL, sl);
        }
        if (bact) {
            uint32_t d = st + brow * RB + acol * 16;
            const __nv_bfloat16* sh = gBh + (size_t)brow * Nq + k0 + acol * 8;
            const __nv_bfloat16* sl = gBl + (size_t)brow * Nq + k0 + acol * 8;
            CP_ASYNC16(d + OFF_BH, sh);
            CP_ASYNC16(d + OFF_BL, sl);
        }
    };

    issue(0); CP_COMMIT();

    // ldmatrix lane-address components (byte offsets within operand tile)
    const int a_r = (lane & 15);                // row within 16-row frag
    const int a_k = (lane >> 4) * 16;           // 16B k-chunk
    const int b_r = ((lane >> 4) << 3) + (lane & 7);   // row within 16-n block
    const int b_k = ((lane >> 3) & 1) * 16;

#pragma unroll 1
    for (int c = 0; c < NC; c++) {
        if (c + 1 < NC) { issue(c + 1); CP_COMMIT(); CP_WAIT1(); }
        else { CP_WAIT0(); }
        __syncthreads();

        const uint32_t st = sbase + (uint32_t)(c & 1) * STAGE;
#pragma unroll
        for (int ks = 0; ks < 2; ks++) {
            uint32_t ah[2][4], al[2][4];
#pragma unroll
            for (int mf = 0; mf < 2; mf++) {
                uint32_t addr = st + (wm * 32 + mf * 16 + a_r) * RB + ks * 32 + a_k;
                ldsm4(addr + OFF_AH, ah[mf]);
                ldsm4(addr + OFF_AL, al[mf]);
            }
            uint32_t bh[NB][4], bl[NB][4];
#pragma unroll
            for (int nb = 0; nb < NB; nb++) {
                uint32_t addr = st + (wn * WN + nb * 16 + b_r) * RB + ks * 32 + b_k;
                ldsm4(addr + OFF_BH, bh[nb]);
                ldsm4(addr + OFF_BL, bl[nb]);
            }
#pragma unroll
            for (int mf = 0; mf < 2; mf++)
#pragma unroll
                for (int nf = 0; nf < NF; nf++) {
                    const int nb = nf >> 1, pr = (nf & 1) * 2;
                    mma16816(acc[mf][nf], ah[mf], bh[nb][pr], bh[nb][pr + 1]);
                    mma16816(acc[mf][nf], ah[mf], bl[nb][pr], bl[nb][pr + 1]);
                    mma16816(acc[mf][nf], al[mf], bh[nb][pr], bh[nb][pr + 1]);
                }
        }
        __syncthreads();
    }

    // epilogue: d0,d1 -> row r, cols c,c+1 ; d2,d3 -> row r+8
    float* yb = Y + (size_t)z * yZ;
#pragma unroll
    for (int mf = 0; mf < 2; mf++)
#pragma unroll
        for (int nf = 0; nf < NF; nf++) {
            int r = m0 + wm * 32 + mf * 16 + (lane >> 2);
            int cj = wn * WN + nf * 8 + (lane & 3) * 2;
            size_t off = (size_t)(cj >> 5) * gstride + (cj & 31);
            float* o0 = yb + (size_t)r * rstride + off;
            float* o1 = yb + (size_t)(r + 8) * rstride + off;
            *(float2*)o0 = make_float2(acc[mf][nf][0], acc[mf][nf][1]);
            *(float2*)o1 = make_float2(acc[mf][nf][2], acc[mf][nf][3]);
        }
}

// ---------------------------------------------------------------------------
// gates1: LSTM gates 0..7
// ---------------------------------------------------------------------------
__global__ __launch_bounds__(256) void gates1_kernel(const float* __restrict__ W,
                                                     const float* __restrict__ bias,
                                                     int t, float* __restrict__ last_c) {
    extern __shared__ float sm[];
    float4* Wp = (float4*)sm;            // 4096 float4
    float4* bp = (float4*)(sm + 16384);  // 128 float4

    const int tid = threadIdx.x;
    for (int idx = tid; idx < 4096; idx += 256) {
        int l = idx & 31, p = (idx >> 5) & 3, k = idx >> 7;
        const float* W0 = W + (2 * p) * (Fq * 2 * Fq) + k * (2 * Fq);
        const float* W1 = W + (2 * p + 1) * (Fq * 2 * Fq) + k * (2 * Fq);
        Wp[idx] = make_float4(W0[l], W0[l + 32], W1[l], W1[l + 32]);
    }
    if (tid < 128) {
        int l = tid & 31, p = tid >> 5;
        bp[p * 32 + l] = make_float4(bias[(2 * p) * 64 + l], bias[(2 * p) * 64 + 32 + l],
                                     bias[(2 * p + 1) * 64 + l], bias[(2 * p + 1) * 64 + 32 + l]);
    }
    __syncthreads();

    const int w = tid >> 5, l = tid & 31;
    const int nrows = Bq * Nq;
    for (int row = blockIdx.x * 8 + w; row < nrows; row += gridDim.x * 8) {
        int b = row >> 12, n = row & (Nq - 1);
        float yx = g_YX[(((size_t)b * Tq + t) * Nq + n) * Fq + l];
        float yh = g_Y1[(size_t)row * (2 * Fq) + l];

        float acc[4][4];
#pragma unroll
        for (int p = 0; p < 4; p++)
#pragma unroll
            for (int q = 0; q < 4; q++) acc[p][q] = 0.0f;

#pragma unroll
        for (int k = 0; k < 32; k++) {
            float ykx = __shfl_sync(0xffffffffu, yx, k);
            float ykh = __shfl_sync(0xffffffffu, yh, k);
#pragma unroll
            for (int p = 0; p < 4; p++) {
                float4 wv = Wp[k * 128 + p * 32 + l];
                acc[p][0] = fmaf(ykx, wv.x, acc[p][0]);
                acc[p][1] = fmaf(ykx, wv.y, acc[p][1]);
                acc[p][2] = fmaf(ykh, wv.z, acc[p][2]);
                acc[p][3] = fmaf(ykh, wv.w, acc[p][3]);
            }
        }

        float s[4];
#pragma unroll
        for (int p = 0; p < 4; p++) {
            float4 bb = bp[p * 32 + l];
            float gx = (acc[p][0] + bb.x) * sigf(acc[p][1] + bb.y);
            float gh = (acc[p][2] + bb.z) * sigf(acc[p][3] + bb.w);
            s[p] = gx + gh;
        }
        float f  = sigf(s[0]);
        float ig = sigf(s[1]);
        float o  = sigf(s[3]);
        size_t ci = (size_t)row * Fq + l;
        float cn = f * g_c[ci] + ig * tanhf(s[2]);
        g_c[ci] = cn;
        g_hmid[ci] = o * tanhf(cn);
        if (t == Tq - 1) last_c[ci] = cn;
    }
}

// ---------------------------------------------------------------------------
// gates2: memory gates 8..13
// ---------------------------------------------------------------------------
__global__ __launch_bounds__(256) void gates2_kernel(const float* __restrict__ W8,
                                                     const float* __restrict__ bias8,
                                                     int t, float* __restrict__ hidden,
                                                     float* __restrict__ last_h,
                                                     float* __restrict__ last_m) {
    extern __shared__ float sm[];
    float4* Wp = (float4*)sm;            // 3072 float4
    float4* bp = (float4*)(sm + 12288);  // 96 float4

    const int tid = threadIdx.x;
    for (int idx = tid; idx < 3072; idx += 256) {
        int k = idx / 96, r = idx % 96, p = r >> 5, l = r & 31;
        const float* W0 = W8 + (2 * p) * (Fq * 2 * Fq) + k * (2 * Fq);
        const float* W1 = W8 + (2 * p + 1) * (Fq * 2 * Fq) + k * (2 * Fq);
        Wp[idx] = make_float4(W0[l], W0[l + 32], W1[l], W1[l + 32]);
    }
    if (tid < 96) {
        int p = tid >> 5, l = tid & 31;
        bp[tid] = make_float4(bias8[(2 * p) * 64 + l], bias8[(2 * p) * 64 + 32 + l],
                              bias8[(2 * p + 1) * 64 + l], bias8[(2 * p + 1) * 64 + 32 + l]);
    }
    __syncthreads();

    const int w = tid >> 5, l = tid & 31;
    const int nrows = Bq * Nq;
    for (int row = blockIdx.x * 8 + w; row < nrows; row += gridDim.x * 8) {
        int b = row >> 12, n = row & (Nq - 1);
        float y2 = g_Y2[(size_t)row * Fq + l];
        float ym = g_Y1[(size_t)row * (2 * Fq) + 32 + l];

        float acc[3][4];
#pragma unroll
        for (int p = 0; p < 3; p++)
#pragma unroll
            for (int q = 0; q < 4; q++) acc[p][q] = 0.0f;

#pragma unroll
        for (int k = 0; k < 32; k++) {
            float yk2 = __shfl_sync(0xffffffffu, y2, k);
            float ykm = __shfl_sync(0xffffffffu, ym, k);
#pragma unroll
            for (int p = 0; p < 3; p++) {
                float4 wv = Wp[k * 96 + p * 32 + l];
                acc[p][0] = fmaf(yk2, wv.x, acc[p][0]);
                acc[p][1] = fmaf(yk2, wv.y, acc[p][1]);
                acc[p][2] = fmaf(ykm, wv.z, acc[p][2]);
                acc[p][3] = fmaf(ykm, wv.w, acc[p][3]);
            }
        }

        float s[3];
#pragma unroll
        for (int p = 0; p < 3; p++) {
            float4 bb = bp[p * 32 + l];
            float gx = (acc[p][0] + bb.x) * sigf(acc[p][1] + bb.y);
            float gh = (acc[p][2] + bb.z) * sigf(acc[p][3] + bb.w);
            s[p] = gx + gh;
        }
        float i2 = sigf(s[0]);
        float gg = sigf(s[1]);
        float o2 = sigf(s[2]);
        float mo = g_S[(size_t)row * (2 * Fq) + 32 + l];
        float mn = i2 * mo + (1.0f - i2) * gg;
        float hn = mn * o2;
        g_S[(size_t)row * (2 * Fq) + l]      = hn;
        g_S[(size_t)row * (2 * Fq) + 32 + l] = mn;
        hidden[(((size_t)b * Tq + t) * Nq + n) * Fq + l] = hn;
        if (t == Tq - 1) {
            last_h[(size_t)row * Fq + l] = hn;
            last_m[(size_t)row * Fq + l] = mn;
        }
    }
}

// ---------------------------------------------------------------------------
// kernel_launch
// ---------------------------------------------------------------------------
extern "C" void kernel_launch(void* const* d_in, const int* in_sizes, int n_in,
                              void* d_out, int out_size) {
    (void)in_sizes; (void)n_in; (void)out_size;
    const float* x    = (const float*)d_in[0];
    const float* adj  = (const float*)d_in[1];
    const float* W    = (const float*)d_in[2];
    const float* bias = (const float*)d_in[3];

    float* hidden = (float*)d_out;
    float* last_h = hidden + (size_t)Bq * Tq * Nq * Fq;
    float* last_c = last_h + (size_t)Bq * Nq * Fq;
    float* last_m = last_c + (size_t)Bq * Nq * Fq;

    float *pYX, *pY1, *pY2, *pS, *pHmid;
    __nv_bfloat16 *pxth, *pxtl, *pSth, *pStl, *phth, *phtl;
    cudaGetSymbolAddress((void**)&pYX,   g_YX);
    cudaGetSymbolAddress((void**)&pY1,   g_Y1);
    cudaGetSymbolAddress((void**)&pY2,   g_Y2);
    cudaGetSymbolAddress((void**)&pS,    g_S);
    cudaGetSymbolAddress((void**)&pHmid, g_hmid);
    cudaGetSymbolAddress((void**)&pxth,  g_xth);
    cudaGetSymbolAddress((void**)&pxtl,  g_xtl);
    cudaGetSymbolAddress((void**)&pSth,  g_Sth);
    cudaGetSymbolAddress((void**)&pStl,  g_Stl);
    cudaGetSymbolAddress((void**)&phth,  g_hth);
    cudaGetSymbolAddress((void**)&phtl,  g_htl);

    const int G1_SMEM = (16384 + 512) * 4;
    const int G2_SMEM = (12288 + 384) * 4;
    const int GEMM64_SMEM = 2 * (2 * 128 * 80 + 2 * 64 * 80);  // 61440
    const int GEMM32_SMEM = 2 * (2 * 128 * 80 + 2 * 32 * 80);  // 51200
    cudaFuncSetAttribute(gates1_kernel, cudaFuncAttributeMaxDynamicSharedMemorySize, G1_SMEM);
    cudaFuncSetAttribute(gates2_kernel, cudaFuncAttributeMaxDynamicSharedMemorySize, G2_SMEM);
    cudaFuncSetAttribute(adj_gemm_mma<64>, cudaFuncAttributeMaxDynamicSharedMemorySize, GEMM64_SMEM);
    cudaFuncSetAttribute(adj_gemm_mma<32>, cudaFuncAttributeMaxDynamicSharedMemorySize, GEMM32_SMEM);

    convert_adj<<<(Bq * Nq * Nq / 4) / 256, 256>>>(adj);
    init_state<<<(Bq * Nq * 2 * Fq + 255) / 256, 256>>>();

    // initial transposed state (h=m=1)
    trans_split<64><<<dim3(Nq / 64, 1, Bq), 256>>>(pS, (long long)Nq * 64, pSth, pStl, (long long)64 * Nq);
    // x transposed+split: slabs [b*12+t][32][n] = [b][384][n]
    trans_split<32><<<dim3(Nq / 64, 1, Bq * Tq), 256>>>(x, (long long)Nq * 32, pxth, pxtl, (long long)32 * Nq);

    // Precompute adj @ x: 24 slabs of BN=64 (t-pairs), A batch = z/6
    adj_gemm_mma<64><<<dim3(Nq / 128, 1, Bq * Tq / 2), 256, GEMM64_SMEM>>>(
        pxth, pxtl, (long long)64 * Nq, 6,
        pYX, (long long)Nq * 64, 32, (long long)Nq * 32);

    for (int t = 0; t < Tq; t++) {
        // Y1 = adj @ [h|m]^T
        adj_gemm_mma<64><<<dim3(Nq / 128, 1, Bq), 256, GEMM64_SMEM>>>(
            pSth, pStl, (long long)64 * Nq, 1, pY1, (long long)Nq * 64, 64, 32LL);
        gates1_kernel<<<512, 256, G1_SMEM>>>(W, bias, t, last_c);
        trans_split<32><<<dim3(Nq / 64, 1, Bq), 256>>>(pHmid, (long long)Nq * 32, phth, phtl, (long long)32 * Nq);
        // Y2 = adj @ h_mid^T
        adj_gemm_mma<32><<<dim3(Nq / 128, 1, Bq), 256, GEMM32_SMEM>>>(
            phth, phtl, (long long)32 * Nq, 1, pY2, (long long)Nq * 32, 32, 32LL);
        gates2_kernel<<<512, 256, G2_SMEM>>>(W + 8 * (Fq * 2 * Fq), bias + 8 * (2 * Fq),
                                             t, hidden, last_h, last_m);
        trans_split<64><<<dim3(Nq / 64, 1, Bq), 256>>>(pS, (long long)Nq * 64, pSth, pStl, (long long)64 * Nq);
    }
}

// round 4
// speedup vs baseline: 2.1586x; 1.1020x over previous
#include <cuda_runtime.h>
#include <cuda_bf16.h>
#include <cstdint>

#define Bq 4
#define Tq 12
#define Nq 4096
#define Fq 32

// ---------------------------------------------------------------------------
// PTX helpers — Ampere-era only (compute_103-safe; tcgen05 is sm_103a-only
// and the harness compiles via the compute_103 virtual arch)
// ---------------------------------------------------------------------------
__device__ __forceinline__ uint32_t smem_to_u32(const void* p) {
    uint32_t a;
    asm("{ .reg .u64 t; cvta.to.shared.u64 t, %1; cvt.u32.u64 %0, t; }" : "=r"(a) : "l"(p));
    return a;
}

#define CP_ASYNC16(dst, src) \
    asm volatile("cp.async.cg.shared.global [%0], [%1], 16;" :: "r"(dst), "l"(src) : "memory")
#define CP_COMMIT() asm volatile("cp.async.commit_group;" ::: "memory")
#define CP_WAIT0()  asm volatile("cp.async.wait_group 0;" ::: "memory")
#define CP_WAIT1()  asm volatile("cp.async.wait_group 1;" ::: "memory")

__device__ __forceinline__ void ldsm4(uint32_t addr, uint32_t* r) {
    asm volatile("ldmatrix.sync.aligned.m8n8.x4.shared.b16 {%0,%1,%2,%3}, [%4];"
                 : "=r"(r[0]), "=r"(r[1]), "=r"(r[2]), "=r"(r[3]) : "r"(addr));
}
__device__ __forceinline__ void mma16816(float* d, const uint32_t* a, uint32_t b0, uint32_t b1) {
    asm volatile("mma.sync.aligned.m16n8k16.row.col.f32.bf16.bf16.f32 "
                 "{%0,%1,%2,%3},{%4,%5,%6,%7},{%8,%9},{%0,%1,%2,%3};"
                 : "+f"(d[0]), "+f"(d[1]), "+f"(d[2]), "+f"(d[3])
                 : "r"(a[0]), "r"(a[1]), "r"(a[2]), "r"(a[3]), "r"(b0), "r"(b1));
}

// ---------------------------------------------------------------------------
// Device scratch
// ---------------------------------------------------------------------------
__device__ __align__(128) __nv_bfloat16 g_Ahi[(size_t)Bq * Nq * Nq];
__device__ __align__(128) __nv_bfloat16 g_Alo[(size_t)Bq * Nq * Nq];
__device__ __align__(128) __nv_bfloat16 g_xth[(size_t)Bq * Tq * Fq * Nq];  // [b][t*32+f][n]
__device__ __align__(128) __nv_bfloat16 g_xtl[(size_t)Bq * Tq * Fq * Nq];
__device__ __align__(128) __nv_bfloat16 g_Sth[(size_t)Bq * 2 * Fq * Nq];   // [b][64][n]  (h|m)
__device__ __align__(128) __nv_bfloat16 g_Stl[(size_t)Bq * 2 * Fq * Nq];
__device__ __align__(128) __nv_bfloat16 g_hth[(size_t)Bq * Fq * Nq];       // [b][32][n]  (h_mid)
__device__ __align__(128) __nv_bfloat16 g_htl[(size_t)Bq * Fq * Nq];

__device__ __align__(128) float g_YX[(size_t)Bq * Tq * Nq * Fq];
__device__ __align__(128) float g_Y1[2 * (size_t)Bq * Nq * 2 * Fq];  // split-K partials
__device__ __align__(128) float g_Y2[2 * (size_t)Bq * Nq * Fq];
__device__ __align__(128) float g_m [(size_t)Bq * Nq * Fq];          // fp32 m state
__device__ __align__(128) float g_c [(size_t)Bq * Nq * Fq];

__device__ __forceinline__ float sigf(float x) { return 1.0f / (1.0f + __expf(-x)); }

// ---------------------------------------------------------------------------
// adj -> bf16 hi/lo split
// ---------------------------------------------------------------------------
__global__ __launch_bounds__(256) void convert_adj(const float* __restrict__ adj) {
    size_t i = (size_t)blockIdx.x * 256 + threadIdx.x;
    float4 v = ((const float4*)adj)[i];
    __nv_bfloat16 h0 = __float2bfloat16(v.x), h1 = __float2bfloat16(v.y);
    __nv_bfloat16 h2 = __float2bfloat16(v.z), h3 = __float2bfloat16(v.w);
    __nv_bfloat16 l0 = __float2bfloat16(v.x - __bfloat162float(h0));
    __nv_bfloat16 l1 = __float2bfloat16(v.y - __bfloat162float(h1));
    __nv_bfloat16 l2 = __float2bfloat16(v.z - __bfloat162float(h2));
    __nv_bfloat16 l3 = __float2bfloat16(v.w - __bfloat162float(h3));
    __nv_bfloat162 hp0 = {h0, h1}, hp1 = {h2, h3}, lp0 = {l0, l1}, lp1 = {l2, l3};
    uint2 hw, lw;
    hw.x = *(uint32_t*)&hp0; hw.y = *(uint32_t*)&hp1;
    lw.x = *(uint32_t*)&lp0; lw.y = *(uint32_t*)&lp1;
    ((uint2*)g_Ahi)[i] = hw;
    ((uint2*)g_Alo)[i] = lw;
}

__global__ void init_state() {
    int i = blockIdx.x * blockDim.x + threadIdx.x;
    if (i < Bq * Nq * Fq) { g_m[i] = 1.0f; g_c[i] = 1.0f; }
    if (i < Bq * 2 * Fq * Nq) {
        g_Sth[i] = __float2bfloat16(1.0f);
        g_Stl[i] = __float2bfloat16(0.0f);
    }
}

// ---------------------------------------------------------------------------
// transpose + bf16 split for x: [z][4096][32] fp32 -> [z][32][4096] bf16 hi/lo
// ---------------------------------------------------------------------------
__global__ __launch_bounds__(256) void trans_split_x(const float* __restrict__ V,
                                                     __nv_bfloat16* __restrict__ Thi,
                                                     __nv_bfloat16* __restrict__ Tlo) {
    __shared__ float tile[64][33];
    const int z = blockIdx.z;
    const int n0 = blockIdx.x * 64;
    const float* v = V + (size_t)z * Nq * 32 + (size_t)n0 * 32;
    const int tid = threadIdx.x;
#pragma unroll
    for (int idx = tid; idx < 64 * 32; idx += 256)
        tile[idx >> 5][idx & 31] = v[idx];
    __syncthreads();
    __nv_bfloat16* th = Thi + (size_t)z * 32 * Nq;
    __nv_bfloat16* tl = Tlo + (size_t)z * 32 * Nq;
#pragma unroll
    for (int idx = tid; idx < 64 * 32; idx += 256) {
        int f = idx >> 6, j = idx & 63;
        float val = tile[j][f];
        __nv_bfloat16 hi = __float2bfloat16(val);
        __nv_bfloat16 lo = __float2bfloat16(val - __bfloat162float(hi));
        th[(size_t)f * Nq + n0 + j] = hi;
        tl[(size_t)f * Nq + n0 + j] = lo;
    }
}

// ---------------------------------------------------------------------------
// split-bf16 mma.sync GEMM with split-K:
//   Y[part=blockIdx.y][z] = adj[z/adiv][k-seg] @ V[z][k-seg]
// A [128 rows][K] bf16 hi/lo; B = V^T [BN rows][K] bf16 hi/lo.
// D = Ahi*Bhi + Ahi*Blo + Alo*Bhi, fp32 register accumulators.
// BM=128, BK=32, 8 warps 4(m) x 2(n). 3-stage cp.async pipeline,
// one __syncthreads per chunk (buffer reuse distance 3 makes the trailing
// barrier unnecessary: passing sync(c) implies all warps finished compute(c-1)).
// ---------------------------------------------------------------------------
template <int BN>
__global__ __launch_bounds__(256, 2) void adj_gemm_mma(
    const __nv_bfloat16* __restrict__ Bhi_g, const __nv_bfloat16* __restrict__ Blo_g,
    long long bZ, int adiv, float* __restrict__ Y, long long yZ,
    int rstride, long long gstride, long long partStride, int nch) {
    constexpr int RB = 80;                 // 64B data + 16B pad
    constexpr int A_BYTES = 128 * RB;
    constexpr int B_BYTES = BN * RB;
    constexpr int OFF_AH = 0, OFF_AL = A_BYTES;
    constexpr int OFF_BH = 2 * A_BYTES, OFF_BL = 2 * A_BYTES + B_BYTES;
    constexpr int STAGE = 2 * A_BYTES + 2 * B_BYTES;
    constexpr int WN = BN / 2;
    constexpr int NF = WN / 8;
    constexpr int NB = (NF + 1) / 2;

    extern __shared__ char smc[];
    const uint32_t sbase = smem_to_u32(smc);
    const int tid = threadIdx.x;
    const int wid = tid >> 5, lane = tid & 31;
    const int wm = wid & 3, wn = wid >> 2;
    const int z = blockIdx.z;
    const int m0 = blockIdx.x * 128;
    const int kbase = blockIdx.y * nch * 32;

    const __nv_bfloat16* gAh = g_Ahi + (size_t)(z / adiv) * Nq * Nq + (size_t)m0 * Nq + kbase;
    const __nv_bfloat16* gAl = g_Alo + (size_t)(z / adiv) * Nq * Nq + (size_t)m0 * Nq + kbase;
    const __nv_bfloat16* gBh = Bhi_g + (size_t)z * bZ + kbase;
    const __nv_bfloat16* gBl = Blo_g + (size_t)z * bZ + kbase;

    const int arow = tid >> 2;
    const int acol = tid & 3;
    const int brow = tid >> 2;
    const bool bact = (BN == 64) || (tid < 128);

    float acc[2][NF][4];
#pragma unroll
    for (int mf = 0; mf < 2; mf++)
#pragma unroll
        for (int nf = 0; nf < NF; nf++)
#pragma unroll
            for (int q = 0; q < 4; q++) acc[mf][nf][q] = 0.0f;

    auto issue = [&](int c) {
        const uint32_t st = sbase + (uint32_t)(c % 3) * STAGE;
        const int k0 = c * 32;
#pragma unroll
        for (int rep = 0; rep < 2; rep++) {
            int r = rep * 64 + arow;
            uint32_t d = st + r * RB + acol * 16;
            CP_ASYNC16(d + OFF_AH, gAh + (size_t)r * Nq + k0 + acol * 8);
            CP_ASYNC16(d + OFF_AL, gAl + (size_t)r * Nq + k0 + acol * 8);
        }
        if (bact) {
            uint32_t d = st + brow * RB + acol * 16;
            CP_ASYNC16(d + OFF_BH, gBh + (size_t)brow * Nq + k0 + acol * 8);
            CP_ASYNC16(d + OFF_BL, gBl + (size_t)brow * Nq + k0 + acol * 8);
        }
    };

    issue(0); CP_COMMIT();
    issue(1); CP_COMMIT();

    const int a_r = (lane & 15);
    const int a_k = (lane >> 4) * 16;
    const int b_r = ((lane >> 4) << 3) + (lane & 7);
    const int b_k = ((lane >> 3) & 1) * 16;

#pragma unroll 1
    for (int c = 0; c < nch; c++) {
        if (c + 1 < nch) { CP_WAIT1(); } else { CP_WAIT0(); }
        __syncthreads();
        if (c + 2 < nch) { issue(c + 2); CP_COMMIT(); }

        const uint32_t st = sbase + (uint32_t)(c % 3) * STAGE;
#pragma unroll
        for (int ks = 0; ks < 2; ks++) {
            uint32_t ah[2][4], al[2][4];
#pragma unroll
            for (int mf = 0; mf < 2; mf++) {
                uint32_t addr = st + (wm * 32 + mf * 16 + a_r) * RB + ks * 32 + a_k;
                ldsm4(addr + OFF_AH, ah[mf]);
                ldsm4(addr + OFF_AL, al[mf]);
            }
            uint32_t bh[NB][4], bl[NB][4];
#pragma unroll
            for (int nb = 0; nb < NB; nb++) {
                uint32_t addr = st + (wn * WN + nb * 16 + b_r) * RB + ks * 32 + b_k;
                ldsm4(addr + OFF_BH, bh[nb]);
                ldsm4(addr + OFF_BL, bl[nb]);
            }
#pragma unroll
            for (int mf = 0; mf < 2; mf++)
#pragma unroll
                for (int nf = 0; nf < NF; nf++) {
                    const int nb = nf >> 1, pr = (nf & 1) * 2;
                    mma16816(acc[mf][nf], ah[mf], bh[nb][pr], bh[nb][pr + 1]);
                    mma16816(acc[mf][nf], ah[mf], bl[nb][pr], bl[nb][pr + 1]);
                    mma16816(acc[mf][nf], al[mf], bh[nb][pr], bh[nb][pr + 1]);
                }
        }
    }

    float* yb = Y + (size_t)blockIdx.y * partStride + (size_t)z * yZ;
#pragma unroll
    for (int mf = 0; mf < 2; mf++)
#pragma unroll
        for (int nf = 0; nf < NF; nf++) {
            int r = m0 + wm * 32 + mf * 16 + (lane >> 2);
            int cj = wn * WN + nf * 8 + (lane & 3) * 2;
            size_t off = (size_t)(cj >> 5) * gstride + (cj & 31);
            float* o0 = yb + (size_t)r * rstride + off;
            float* o1 = yb + (size_t)(r + 8) * rstride + off;
            *(float2*)o0 = make_float2(acc[mf][nf][0], acc[mf][nf][1]);
            *(float2*)o1 = make_float2(acc[mf][nf][2], acc[mf][nf][3]);
        }
}

// ---------------------------------------------------------------------------
// gates1: LSTM gates 0..7; sums split-K partials of Y1; writes h_mid directly
// as transposed bf16 hi/lo (feeds next GEMM, no separate transpose kernel).
// ---------------------------------------------------------------------------
__global__ __launch_bounds__(256) void gates1_kernel(const float* __restrict__ W,
                                                     const float* __restrict__ bias,
                                                     int t, float* __restrict__ last_c) {
    extern __shared__ float sm[];
    float4* Wp = (float4*)sm;
    float4* bp = (float4*)(sm + 16384);
    const long long PS1 = (long long)Bq * Nq * 64;

    const int tid = threadIdx.x;
    for (int idx = tid; idx < 4096; idx += 256) {
        int l = idx & 31, p = (idx >> 5) & 3, k = idx >> 7;
        const float* W0 = W + (2 * p) * (Fq * 2 * Fq) + k * (2 * Fq);
        const float* W1 = W + (2 * p + 1) * (Fq * 2 * Fq) + k * (2 * Fq);
        Wp[idx] = make_float4(W0[l], W0[l + 32], W1[l], W1[l + 32]);
    }
    if (tid < 128) {
        int l = tid & 31, p = tid >> 5;
        bp[p * 32 + l] = make_float4(bias[(2 * p) * 64 + l], bias[(2 * p) * 64 + 32 + l],
                                     bias[(2 * p + 1) * 64 + l], bias[(2 * p + 1) * 64 + 32 + l]);
    }
    __syncthreads();

    const int w = tid >> 5, l = tid & 31;
    const int nrows = Bq * Nq;
    for (int row = blockIdx.x * 8 + w; row < nrows; row += gridDim.x * 8) {
        int b = row >> 12, n = row & (Nq - 1);
        float yx = g_YX[(((size_t)b * Tq + t) * Nq + n) * Fq + l];
        float yh = g_Y1[(size_t)row * 64 + l] + g_Y1[PS1 + (size_t)row * 64 + l];

        float acc[4][4];
#pragma unroll
        for (int p = 0; p < 4; p++)
#pragma unroll
            for (int q = 0; q < 4; q++) acc[p][q] = 0.0f;

#pragma unroll
        for (int k = 0; k < 32; k++) {
            float ykx = __shfl_sync(0xffffffffu, yx, k);
            float ykh = __shfl_sync(0xffffffffu, yh, k);
#pragma unroll
            for (int p = 0; p < 4; p++) {
                float4 wv = Wp[k * 128 + p * 32 + l];
                acc[p][0] = fmaf(ykx, wv.x, acc[p][0]);
                acc[p][1] = fmaf(ykx, wv.y, acc[p][1]);
                acc[p][2] = fmaf(ykh, wv.z, acc[p][2]);
                acc[p][3] = fmaf(ykh, wv.w, acc[p][3]);
            }
        }

        float s[4];
#pragma unroll
        for (int p = 0; p < 4; p++) {
            float4 bb = bp[p * 32 + l];
            float gx = (acc[p][0] + bb.x) * sigf(acc[p][1] + bb.y);
            float gh = (acc[p][2] + bb.z) * sigf(acc[p][3] + bb.w);
            s[p] = gx + gh;
        }
        float f  = sigf(s[0]);
        float ig = sigf(s[1]);
        float o  = sigf(s[3]);
        size_t ci = (size_t)row * Fq + l;
        float cn = f * g_c[ci] + ig * tanhf(s[2]);
        g_c[ci] = cn;
        float hm = o * tanhf(cn);
        size_t ti = ((size_t)b * Fq + l) * Nq + n;   // transposed [b][l][n]
        __nv_bfloat16 hi = __float2bfloat16(hm);
        g_hth[ti] = hi;
        g_htl[ti] = __float2bfloat16(hm - __bfloat162float(hi));
        if (t == Tq - 1) last_c[ci] = cn;
    }
}

// ---------------------------------------------------------------------------
// gates2: memory gates 8..13; sums split-K partials; writes new [h|m]
// transposed bf16 hi/lo for the next step's GEMM.
// ---------------------------------------------------------------------------
__global__ __launch_bounds__(256) void gates2_kernel(const float* __restrict__ W8,
                                                     const float* __restrict__ bias8,
                                                     int t, float* __restrict__ hidden,
                                                     float* __restrict__ last_h,
                                                     float* __restrict__ last_m) {
    extern __shared__ float sm[];
    float4* Wp = (float4*)sm;
    float4* bp = (float4*)(sm + 12288);
    const long long PS1 = (long long)Bq * Nq * 64;
    const long long PS2 = (long long)Bq * Nq * 32;

    const int tid = threadIdx.x;
    for (int idx = tid; idx < 3072; idx += 256) {
        int k = idx / 96, r = idx % 96, p = r >> 5, l = r & 31;
        const float* W0 = W8 + (2 * p) * (Fq * 2 * Fq) + k * (2 * Fq);
        const float* W1 = W8 + (2 * p + 1) * (Fq * 2 * Fq) + k * (2 * Fq);
        Wp[idx] = make_float4(W0[l], W0[l + 32], W1[l], W1[l + 32]);
    }
    if (tid < 96) {
        int p = tid >> 5, l = tid & 31;
        bp[tid] = make_float4(bias8[(2 * p) * 64 + l], bias8[(2 * p) * 64 + 32 + l],
                              bias8[(2 * p + 1) * 64 + l], bias8[(2 * p + 1) * 64 + 32 + l]);
    }
    __syncthreads();

    const int w = tid >> 5, l = tid & 31;
    const int nrows = Bq * Nq;
    for (int row = blockIdx.x * 8 + w; row < nrows; row += gridDim.x * 8) {
        int b = row >> 12, n = row & (Nq - 1);
        float y2 = g_Y2[(size_t)row * 32 + l] + g_Y2[PS2 + (size_t)row * 32 + l];
        float ym = g_Y1[(size_t)row * 64 + 32 + l] + g_Y1[PS1 + (size_t)row * 64 + 32 + l];

        float acc[3][4];
#pragma unroll
        for (int p = 0; p < 3; p++)
#pragma unroll
            for (int q = 0; q < 4; q++) acc[p][q] = 0.0f;

#pragma unroll
        for (int k = 0; k < 32; k++) {
            float yk2 = __shfl_sync(0xffffffffu, y2, k);
            float ykm = __shfl_sync(0xffffffffu, ym, k);
#pragma unroll
            for (int p = 0; p < 3; p++) {
                float4 wv = Wp[k * 96 + p * 32 + l];
                acc[p][0] = fmaf(yk2, wv.x, acc[p][0]);
                acc[p][1] = fmaf(yk2, wv.y, acc[p][1]);
                acc[p][2] = fmaf(ykm, wv.z, acc[p][2]);
                acc[p][3] = fmaf(ykm, wv.w, acc[p][3]);
            }
        }

        float s[3];
#pragma unroll
        for (int p = 0; p < 3; p++) {
            float4 bb = bp[p * 32 + l];
            float gx = (acc[p][0] + bb.x) * sigf(acc[p][1] + bb.y);
            float gh = (acc[p][2] + bb.z) * sigf(acc[p][3] + bb.w);
            s[p] = gx + gh;
        }
        float i2 = sigf(s[0]);
        float gg = sigf(s[1]);
        float o2 = sigf(s[2]);
        size_t ci = (size_t)row * Fq + l;
        float mo = g_m[ci];
        float mn = i2 * mo + (1.0f - i2) * gg;
        float hn = mn * o2;
        g_m[ci] = mn;
        size_t th = ((size_t)b * 64 + l) * Nq + n;        // h at [b][l][n]
        size_t tm = ((size_t)b * 64 + 32 + l) * Nq + n;   // m at [b][32+l][n]
        __nv_bfloat16 hh = __float2bfloat16(hn);
        __nv_bfloat16 mh = __float2bfloat16(mn);
        g_Sth[th] = hh;
        g_Stl[th] = __float2bfloat16(hn - __bfloat162float(hh));
        g_Sth[tm] = mh;
        g_Stl[tm] = __float2bfloat16(mn - __bfloat162float(mh));
        hidden[(((size_t)b * Tq + t) * Nq + n) * Fq + l] = hn;
        if (t == Tq - 1) {
            last_h[ci] = hn;
            last_m[ci] = mn;
        }
    }
}

// ---------------------------------------------------------------------------
// kernel_launch
// ---------------------------------------------------------------------------
extern "C" void kernel_launch(void* const* d_in, const int* in_sizes, int n_in,
                              void* d_out, int out_size) {
    (void)in_sizes; (void)n_in; (void)out_size;
    const float* x    = (const float*)d_in[0];
    const float* adj  = (const float*)d_in[1];
    const float* W    = (const float*)d_in[2];
    const float* bias = (const float*)d_in[3];

    float* hidden = (float*)d_out;
    float* last_h = hidden + (size_t)Bq * Tq * Nq * Fq;
    float* last_c = last_h + (size_t)Bq * Nq * Fq;
    float* last_m = last_c + (size_t)Bq * Nq * Fq;

    float *pYX, *pY1, *pY2;
    __nv_bfloat16 *pxth, *pxtl, *pSth, *pStl, *phth, *phtl;
    cudaGetSymbolAddress((void**)&pYX,  g_YX);
    cudaGetSymbolAddress((void**)&pY1,  g_Y1);
    cudaGetSymbolAddress((void**)&pY2,  g_Y2);
    cudaGetSymbolAddress((void**)&pxth, g_xth);
    cudaGetSymbolAddress((void**)&pxtl, g_xtl);
    cudaGetSymbolAddress((void**)&pSth, g_Sth);
    cudaGetSymbolAddress((void**)&pStl, g_Stl);
    cudaGetSymbolAddress((void**)&phth, g_hth);
    cudaGetSymbolAddress((void**)&phtl, g_htl);

    const int G1_SMEM = (16384 + 512) * 4;
    const int G2_SMEM = (12288 + 384) * 4;
    const int GEMM64_SMEM = 3 * (2 * 128 * 80 + 2 * 64 * 80);  // 92160
    const int GEMM32_SMEM = 3 * (2 * 128 * 80 + 2 * 32 * 80);  // 76800
    cudaFuncSetAttribute(gates1_kernel, cudaFuncAttributeMaxDynamicSharedMemorySize, G1_SMEM);
    cudaFuncSetAttribute(gates2_kernel, cudaFuncAttributeMaxDynamicSharedMemorySize, G2_SMEM);
    cudaFuncSetAttribute(adj_gemm_mma<64>, cudaFuncAttributeMaxDynamicSharedMemorySize, GEMM64_SMEM);
    cudaFuncSetAttribute(adj_gemm_mma<32>, cudaFuncAttributeMaxDynamicSharedMemorySize, GEMM32_SMEM);

    convert_adj<<<(Bq * Nq * Nq / 4) / 256, 256>>>(adj);
    init_state<<<(Bq * 2 * Fq * Nq + 255) / 256, 256>>>();

    // x transposed+split: slabs [b*12+t][32][n]
    trans_split_x<<<dim3(Nq / 64, 1, Bq * Tq), 256>>>(x, pxth, pxtl);

    // Precompute adj @ x: 24 slabs of BN=64 (t-pairs), full-K, adiv=6
    adj_gemm_mma<64><<<dim3(Nq / 128, 1, Bq * Tq / 2), 256, GEMM64_SMEM>>>(
        pxth, pxtl, (long long)64 * Nq, 6,
        pYX, (long long)Nq * 64, 32, (long long)Nq * 32, 0LL, Nq / 32);

    const long long PS1 = (long long)Bq * Nq * 64;
    const long long PS2 = (long long)Bq * Nq * 32;
    for (int t = 0; t < Tq; t++) {
        // Y1 = adj @ [h|m]^T   (split-K=2)
        adj_gemm_mma<64><<<dim3(Nq / 128, 2, Bq), 256, GEMM64_SMEM>>>(
            pSth, pStl, (long long)64 * Nq, 1, pY1, (long long)Nq * 64,
            64, 32LL, PS1, Nq / 64);
        gates1_kernel<<<512, 256, G1_SMEM>>>(W, bias, t, last_c);
        // Y2 = adj @ h_mid^T   (split-K=2)
        adj_gemm_mma<32><<<dim3(Nq / 128, 2, Bq), 256, GEMM32_SMEM>>>(
            phth, phtl, (long long)32 * Nq, 1, pY2, (long long)Nq * 32,
            32, 32LL, PS2, Nq / 64);
        gates2_kernel<<<512, 256, G2_SMEM>>>(W + 8 * (Fq * 2 * Fq), bias + 8 * (2 * Fq),
                                             t, hidden, last_h, last_m);
    }
}